// round 1
// baseline (speedup 1.0000x reference)
#include <cuda_runtime.h>
#include <cuda_bf16.h>

#define T_ 2
#define C_ 64
#define H_ 160
#define W_ 160
#define KS 7
#define K2 49
#define NSPIX 196
#define FAN 3136

// scratch (no cudaMalloc allowed)
__device__ float g_sums[T_*NSPIX*C_];
__device__ float g_cnts[T_*NSPIX];
__device__ float g_pwd[T_*NSPIX*NSPIX];
__device__ float g_Wt[K2*C_*C_];   // [k][c][o], o contiguous

__device__ __forceinline__ int refl(int i, int n){
    if (i < 0) i = -i;
    if (i >= n) i = 2*n - 2 - i;
    return i;
}

__global__ void zero_kernel(){
    int i = blockIdx.x*blockDim.x + threadIdx.x;
    if (i < T_*NSPIX*C_) g_sums[i] = 0.f;
    if (i < T_*NSPIX)    g_cnts[i] = 0.f;
}

// W_lin[o, c*49+k] -> g_Wt[(k*64+c)*64+o]
__global__ void wt_kernel(const float* __restrict__ W){
    int i = blockIdx.x*blockDim.x + threadIdx.x;
    if (i >= K2*C_*C_) return;
    int o = i & 63;
    int c = (i >> 6) & 63;
    int k = i >> 12;
    g_Wt[i] = W[o*FAN + c*K2 + k];
}

__global__ void accum_kernel(const float* __restrict__ x, const int* __restrict__ spix){
    int idx = blockIdx.x*blockDim.x + threadIdx.x;
    if (idx >= T_*H_*W_) return;
    int t = idx / (H_*W_);
    int s = spix[idx];
    atomicAdd(&g_cnts[t*NSPIX + s], 1.0f);
    const float* xp = x + (size_t)t*C_*H_*W_ + (idx - t*H_*W_);
    float* dst = &g_sums[(t*NSPIX + s)*C_];
    #pragma unroll 8
    for (int c = 0; c < C_; c++)
        atomicAdd(&dst[c], xp[(size_t)c*H_*W_]);
}

__global__ void pwd_kernel(){
    int t = blockIdx.x / NSPIX, s = blockIdx.x % NSPIX;
    __shared__ float ds[C_];
    int tid = threadIdx.x;
    if (tid < C_) ds[tid] = g_sums[(t*NSPIX+s)*C_ + tid] / fmaxf(g_cnts[t*NSPIX+s], 1.f);
    __syncthreads();
    int u = tid;
    if (u < NSPIX){
        float cinv = 1.f / fmaxf(g_cnts[t*NSPIX+u], 1.f);
        float dot = 0.f, squ = 0.f, sqs = 0.f;
        for (int c = 0; c < C_; c++){
            float du = g_sums[(t*NSPIX+u)*C_ + c] * cinv;
            float a  = ds[c];
            dot += a*du; squ += du*du; sqs += a*a;
        }
        g_pwd[(t*NSPIX+s)*NSPIX + u] = fmaxf(sqs + squ - 2.f*dot, 0.f);
    }
}

#define TH 8
#define TW 16
#define CCH 16
#define XR (TH+6)     // 14
#define XC (TW+6)     // 22
#define NPIX (TH*TW)  // 128

__global__ void __launch_bounds__(256, 3) main_kernel(
    const float* __restrict__ x, const int* __restrict__ spix,
    const float* __restrict__ b_lin, const float* __restrict__ w_scale,
    const float* __restrict__ b_scale, float* __restrict__ out)
{
    __shared__ float xs[CCH*XR*XC];                    // 4928 f
    __shared__ __align__(16) float wk[C_*CCH];         // 1024 f (aliased as scale in phase 1/2)
    __shared__ float rw[NPIX*K2];                      // 6272 f
    float* scale_s = wk;

    int tid = threadIdx.x;
    int t   = blockIdx.z;
    int gh0 = blockIdx.y*TH, gw0 = blockIdx.x*TW;

    // ---- phase 1: per-pixel scale = 10*softplus(dot(w_scale, xn) + b0) ----
    if (tid < NPIX){
        int gh = gh0 + tid/TW, gw = gw0 + (tid % TW);
        const float* xp = x + (size_t)t*C_*H_*W_ + gh*W_ + gw;
        float nsq = 0.f, dot = 0.f;
        #pragma unroll 8
        for (int c = 0; c < C_; c++){
            float v = xp[(size_t)c*H_*W_];
            nsq += v*v;
            dot += w_scale[c]*v;
        }
        float z  = dot / (sqrtf(nsq) + 1e-10f) + b_scale[0];
        float sp = fmaxf(z, 0.f) + log1pf(expf(-fabsf(z)));   // logaddexp(z, 0)
        scale_s[tid] = 10.f * sp;
    }
    __syncthreads();

    // ---- phase 2: rw[p][k] = exp(-scale * pwd[s_center, nb_k]) ----
    for (int item = tid; item < NPIX*K2; item += 256){
        int p  = item / K2, k = item - p*K2;
        int ki = k / KS,  kj = k - ki*KS;
        int gh = gh0 + p/TW, gw = gw0 + (p % TW);
        int rh = refl(gh + ki - 3, H_), rc = refl(gw + kj - 3, W_);
        int sc = spix[(t*H_ + gh)*W_ + gw];
        int nb = spix[(t*H_ + rh)*W_ + rc];
        rw[item] = expf(-scale_s[p] * g_pwd[(t*NSPIX + sc)*NSPIX + nb]);
    }
    __syncthreads();
    if (tid < NPIX){
        float m = 0.f;
        #pragma unroll
        for (int k = 0; k < K2; k++) m = fmaxf(m, rw[tid*K2 + k]);
        float inv = 1.f / (1e-5f + m);
        #pragma unroll
        for (int k = 0; k < K2; k++) rw[tid*K2 + k] *= inv;
    }
    __syncthreads();

    // ---- phase 3: out[o] = b[o] + sum_{k,c} rw_k * W[o,c,k] * x_patch ----
    float acc[4][8];
    #pragma unroll
    for (int a = 0; a < 4; a++)
        #pragma unroll
        for (int b = 0; b < 8; b++) acc[a][b] = 0.f;

    int o8 = (tid & 7) * 8;        // 8 output channels
    int pg = tid >> 3;             // pixel group: 4 consecutive-w pixels
    int pr = pg >> 2;              // tile row 0..7
    int pc = (pg & 3) * 4;         // tile col 0,4,8,12
    int pbase = pr*TW + pc;

    for (int cc = 0; cc < C_; cc += CCH){
        // load x halo tile for this channel chunk (reflect-indexed)
        for (int i = tid; i < CCH*XR*XC; i += 256){
            int c = i / (XR*XC);
            int rem = i - c*(XR*XC);
            int r = rem / XC, col = rem - r*XC;
            int rh = refl(gh0 + r - 3, H_), rc2 = refl(gw0 + col - 3, W_);
            xs[i] = x[((size_t)(t*C_ + cc + c)*H_ + rh)*W_ + rc2];
        }
        __syncthreads();

        for (int k = 0; k < K2; k++){
            // load W slice [cc..cc+15][o] for this k (contiguous, coalesced)
            for (int i = tid; i < C_*CCH; i += 256)
                wk[i] = g_Wt[(k*C_ + cc)*C_ + i];
            __syncthreads();

            int ki = k / KS, kj = k - ki*KS;
            float r0 = rw[(pbase+0)*K2 + k];
            float r1 = rw[(pbase+1)*K2 + k];
            float r2 = rw[(pbase+2)*K2 + k];
            float r3 = rw[(pbase+3)*K2 + k];
            int xb = (pr + ki)*XC + (pc + kj);

            #pragma unroll
            for (int c = 0; c < CCH; c++){
                const float* xrow = &xs[c*(XR*XC) + xb];
                float xv[4];
                xv[0] = xrow[0]*r0; xv[1] = xrow[1]*r1;
                xv[2] = xrow[2]*r2; xv[3] = xrow[3]*r3;
                float wv[8];
                *(float4*)&wv[0] = *(const float4*)&wk[c*C_ + o8];
                *(float4*)&wv[4] = *(const float4*)&wk[c*C_ + o8 + 4];
                #pragma unroll
                for (int pp = 0; pp < 4; pp++)
                    #pragma unroll
                    for (int oo = 0; oo < 8; oo++)
                        acc[pp][oo] += xv[pp]*wv[oo];
            }
            __syncthreads();   // protect wk (and xs on last k) before overwrite
        }
    }

    // ---- epilogue ----
    int gh = gh0 + pr, gw = gw0 + pc;
    #pragma unroll
    for (int oo = 0; oo < 8; oo++){
        float b = b_lin[o8 + oo];
        float* op = out + ((size_t)(t*C_ + o8 + oo)*H_ + gh)*W_ + gw;
        #pragma unroll
        for (int pp = 0; pp < 4; pp++)
            op[pp] = acc[pp][oo] + b;
    }
}

extern "C" void kernel_launch(void* const* d_in, const int* in_sizes, int n_in,
                              void* d_out, int out_size)
{
    const float* x       = (const float*)d_in[0];
    const int*   spix    = (const int*)  d_in[1];
    const float* W       = (const float*)d_in[2];
    const float* b_lin   = (const float*)d_in[3];
    const float* w_scale = (const float*)d_in[4];
    const float* b_scale = (const float*)d_in[5];
    float* out = (float*)d_out;

    zero_kernel <<<(T_*NSPIX*C_ + 255)/256, 256>>>();
    wt_kernel   <<<(K2*C_*C_   + 255)/256, 256>>>(W);
    accum_kernel<<<(T_*H_*W_   + 255)/256, 256>>>(x, spix);
    pwd_kernel  <<<T_*NSPIX, 256>>>();

    dim3 grid(W_/TW, H_/TH, T_);
    main_kernel<<<grid, 256>>>(x, spix, b_lin, w_scale, b_scale, out);
}

// round 2
// speedup vs baseline: 1.0007x; 1.0007x over previous
#include <cuda_runtime.h>
#include <cuda_bf16.h>

#define T_ 2
#define C_ 64
#define H_ 160
#define W_ 160
#define KS 7
#define K2 49
#define NSPIX 196
#define FAN 3136

// scratch (no cudaMalloc allowed)
__device__ float g_sums[T_*NSPIX*C_];
__device__ float g_cnts[T_*NSPIX];
__device__ float g_pwd[T_*NSPIX*NSPIX];
__device__ float g_Wt[K2*C_*C_];   // [k][c][o], o contiguous

__device__ __forceinline__ int refl(int i, int n){
    if (i < 0) i = -i;
    if (i >= n) i = 2*n - 2 - i;
    return i;
}

__global__ void zero_kernel(){
    int i = blockIdx.x*blockDim.x + threadIdx.x;
    if (i < T_*NSPIX*C_) g_sums[i] = 0.f;
    if (i < T_*NSPIX)    g_cnts[i] = 0.f;
}

// W_lin[o, c*49+k] -> g_Wt[(k*64+c)*64+o]
__global__ void wt_kernel(const float* __restrict__ W){
    int i = blockIdx.x*blockDim.x + threadIdx.x;
    if (i >= K2*C_*C_) return;
    int o = i & 63;
    int c = (i >> 6) & 63;
    int k = i >> 12;
    g_Wt[i] = W[o*FAN + c*K2 + k];
}

__global__ void accum_kernel(const float* __restrict__ x, const int* __restrict__ spix){
    int idx = blockIdx.x*blockDim.x + threadIdx.x;
    if (idx >= T_*H_*W_) return;
    int t = idx / (H_*W_);
    int s = spix[idx];
    atomicAdd(&g_cnts[t*NSPIX + s], 1.0f);
    const float* xp = x + (size_t)t*C_*H_*W_ + (idx - t*H_*W_);
    float* dst = &g_sums[(t*NSPIX + s)*C_];
    #pragma unroll 8
    for (int c = 0; c < C_; c++)
        atomicAdd(&dst[c], xp[(size_t)c*H_*W_]);
}

__global__ void pwd_kernel(){
    int t = blockIdx.x / NSPIX, s = blockIdx.x % NSPIX;
    __shared__ float ds[C_];
    int tid = threadIdx.x;
    if (tid < C_) ds[tid] = g_sums[(t*NSPIX+s)*C_ + tid] / fmaxf(g_cnts[t*NSPIX+s], 1.f);
    __syncthreads();
    int u = tid;
    if (u < NSPIX){
        float cinv = 1.f / fmaxf(g_cnts[t*NSPIX+u], 1.f);
        float dot = 0.f, squ = 0.f, sqs = 0.f;
        for (int c = 0; c < C_; c++){
            float du = g_sums[(t*NSPIX+u)*C_ + c] * cinv;
            float a  = ds[c];
            dot += a*du; squ += du*du; sqs += a*a;
        }
        g_pwd[(t*NSPIX+s)*NSPIX + u] = fmaxf(sqs + squ - 2.f*dot, 0.f);
    }
}

#define TH 8
#define TW 16
#define CCH 16
#define XR (TH+6)     // 14
#define XC (TW+6)     // 22
#define NPIX (TH*TW)  // 128

__global__ void __launch_bounds__(256, 3) main_kernel(
    const float* __restrict__ x, const int* __restrict__ spix,
    const float* __restrict__ b_lin, const float* __restrict__ w_scale,
    const float* __restrict__ b_scale, float* __restrict__ out)
{
    __shared__ float xs[CCH*XR*XC];                    // 4928 f
    __shared__ __align__(16) float wk[C_*CCH];         // 1024 f (aliased as scale in phase 1/2)
    __shared__ float rw[NPIX*K2];                      // 6272 f
    float* scale_s = wk;

    int tid = threadIdx.x;
    int t   = blockIdx.z;
    int gh0 = blockIdx.y*TH, gw0 = blockIdx.x*TW;

    // ---- phase 1: per-pixel scale = 10*softplus(dot(w_scale, xn) + b0) ----
    if (tid < NPIX){
        int gh = gh0 + tid/TW, gw = gw0 + (tid % TW);
        const float* xp = x + (size_t)t*C_*H_*W_ + gh*W_ + gw;
        float nsq = 0.f, dot = 0.f;
        #pragma unroll 8
        for (int c = 0; c < C_; c++){
            float v = xp[(size_t)c*H_*W_];
            nsq += v*v;
            dot += w_scale[c]*v;
        }
        float z  = dot / (sqrtf(nsq) + 1e-10f) + b_scale[0];
        float sp = fmaxf(z, 0.f) + log1pf(expf(-fabsf(z)));   // logaddexp(z, 0)
        scale_s[tid] = 10.f * sp;
    }
    __syncthreads();

    // ---- phase 2: rw[p][k] = exp(-scale * pwd[s_center, nb_k]) ----
    for (int item = tid; item < NPIX*K2; item += 256){
        int p  = item / K2, k = item - p*K2;
        int ki = k / KS,  kj = k - ki*KS;
        int gh = gh0 + p/TW, gw = gw0 + (p % TW);
        int rh = refl(gh + ki - 3, H_), rc = refl(gw + kj - 3, W_);
        int sc = spix[(t*H_ + gh)*W_ + gw];
        int nb = spix[(t*H_ + rh)*W_ + rc];
        rw[item] = expf(-scale_s[p] * g_pwd[(t*NSPIX + sc)*NSPIX + nb]);
    }
    __syncthreads();
    if (tid < NPIX){
        float m = 0.f;
        #pragma unroll
        for (int k = 0; k < K2; k++) m = fmaxf(m, rw[tid*K2 + k]);
        float inv = 1.f / (1e-5f + m);
        #pragma unroll
        for (int k = 0; k < K2; k++) rw[tid*K2 + k] *= inv;
    }
    __syncthreads();

    // ---- phase 3: out[o] = b[o] + sum_{k,c} rw_k * W[o,c,k] * x_patch ----
    float acc[4][8];
    #pragma unroll
    for (int a = 0; a < 4; a++)
        #pragma unroll
        for (int b = 0; b < 8; b++) acc[a][b] = 0.f;

    int o8 = (tid & 7) * 8;        // 8 output channels
    int pg = tid >> 3;             // pixel group: 4 consecutive-w pixels
    int pr = pg >> 2;              // tile row 0..7
    int pc = (pg & 3) * 4;         // tile col 0,4,8,12
    int pbase = pr*TW + pc;

    for (int cc = 0; cc < C_; cc += CCH){
        // load x halo tile for this channel chunk (reflect-indexed)
        for (int i = tid; i < CCH*XR*XC; i += 256){
            int c = i / (XR*XC);
            int rem = i - c*(XR*XC);
            int r = rem / XC, col = rem - r*XC;
            int rh = refl(gh0 + r - 3, H_), rc2 = refl(gw0 + col - 3, W_);
            xs[i] = x[((size_t)(t*C_ + cc + c)*H_ + rh)*W_ + rc2];
        }
        __syncthreads();

        for (int k = 0; k < K2; k++){
            // load W slice [cc..cc+15][o] for this k (contiguous, coalesced)
            for (int i = tid; i < C_*CCH; i += 256)
                wk[i] = g_Wt[(k*C_ + cc)*C_ + i];
            __syncthreads();

            int ki = k / KS, kj = k - ki*KS;
            float r0 = rw[(pbase+0)*K2 + k];
            float r1 = rw[(pbase+1)*K2 + k];
            float r2 = rw[(pbase+2)*K2 + k];
            float r3 = rw[(pbase+3)*K2 + k];
            int xb = (pr + ki)*XC + (pc + kj);

            #pragma unroll
            for (int c = 0; c < CCH; c++){
                const float* xrow = &xs[c*(XR*XC) + xb];
                float xv[4];
                xv[0] = xrow[0]*r0; xv[1] = xrow[1]*r1;
                xv[2] = xrow[2]*r2; xv[3] = xrow[3]*r3;
                float wv[8];
                *(float4*)&wv[0] = *(const float4*)&wk[c*C_ + o8];
                *(float4*)&wv[4] = *(const float4*)&wk[c*C_ + o8 + 4];
                #pragma unroll
                for (int pp = 0; pp < 4; pp++)
                    #pragma unroll
                    for (int oo = 0; oo < 8; oo++)
                        acc[pp][oo] += xv[pp]*wv[oo];
            }
            __syncthreads();   // protect wk (and xs on last k) before overwrite
        }
    }

    // ---- epilogue ----
    int gh = gh0 + pr, gw = gw0 + pc;
    #pragma unroll
    for (int oo = 0; oo < 8; oo++){
        float b = b_lin[o8 + oo];
        float* op = out + ((size_t)(t*C_ + o8 + oo)*H_ + gh)*W_ + gw;
        #pragma unroll
        for (int pp = 0; pp < 4; pp++)
            op[pp] = acc[pp][oo] + b;
    }
}

extern "C" void kernel_launch(void* const* d_in, const int* in_sizes, int n_in,
                              void* d_out, int out_size)
{
    const float* x       = (const float*)d_in[0];
    const int*   spix    = (const int*)  d_in[1];
    const float* W       = (const float*)d_in[2];
    const float* b_lin   = (const float*)d_in[3];
    const float* w_scale = (const float*)d_in[4];
    const float* b_scale = (const float*)d_in[5];
    float* out = (float*)d_out;

    zero_kernel <<<(T_*NSPIX*C_ + 255)/256, 256>>>();
    wt_kernel   <<<(K2*C_*C_   + 255)/256, 256>>>(W);
    accum_kernel<<<(T_*H_*W_   + 255)/256, 256>>>(x, spix);
    pwd_kernel  <<<T_*NSPIX, 256>>>();

    dim3 grid(W_/TW, H_/TH, T_);
    main_kernel<<<grid, 256>>>(x, spix, b_lin, w_scale, b_scale, out);
}

// round 4
// speedup vs baseline: 3.3110x; 3.3087x over previous
#include <cuda_runtime.h>
#include <cuda_bf16.h>
#include <cstdint>

#define T_ 2
#define C_ 64
#define H_ 160
#define W_ 160
#define KS 7
#define K2 49
#define NSPIX 196
#define FAN 3136

#define TH 8
#define TW 8
#define NPIX 64        // TH*TW
#define XR 14          // TH+6
#define XC 14          // TW+6
#define NS 196         // XR*XC
#define HROW 272       // 128 hi + 128 lo + 16 pad (272B = 68 words == 4 mod 32 banks)

// ---- dynamic smem layout (bytes) ----
#define OFF_HALO   0                   // 196*272 = 53312
#define OFF_B      53312               // 2 bufs * 16384 = 32768
#define OFF_RW     86080               // 64*49*4 = 12544
#define OFF_SCALE  98624               // 64*4 = 256
#define SMEM_MAIN  98944

#define PWD_SMEM   (64*196*4 + 196*4)  // 50960

// ---- global scratch ----
__device__ float g_sums[T_*NSPIX*C_];
__device__ float g_cnts[T_*NSPIX];
__device__ float g_pwd[T_*NSPIX*NSPIX];
// per k: [hi 8192B][lo 8192B], each 64o x 64c bf16, XOR-16B swizzled rows
__device__ __align__(16) __nv_bfloat16 g_Wsp[K2*2*C_*C_];

__device__ __forceinline__ int refl(int i, int n){
    if (i < 0) i = -i;
    if (i >= n) i = 2*n - 2 - i;
    return i;
}

__device__ __forceinline__ uint32_t smem_u32(const void* p){
    uint32_t a;
    asm("{ .reg .u64 t; cvta.to.shared.u64 t, %1; cvt.u32.u64 %0, t; }" : "=r"(a) : "l"(p));
    return a;
}

__device__ __forceinline__ void ldsm4(uint32_t* r, uint32_t addr){
    asm volatile("ldmatrix.sync.aligned.m8n8.x4.shared.b16 {%0,%1,%2,%3}, [%4];"
        : "=r"(r[0]), "=r"(r[1]), "=r"(r[2]), "=r"(r[3]) : "r"(addr));
}

__device__ __forceinline__ void mma16816(float* d, const uint32_t* a, const uint32_t* b){
    asm volatile("mma.sync.aligned.m16n8k16.row.col.f32.bf16.bf16.f32 "
        "{%0,%1,%2,%3}, {%4,%5,%6,%7}, {%8,%9}, {%0,%1,%2,%3};"
        : "+f"(d[0]), "+f"(d[1]), "+f"(d[2]), "+f"(d[3])
        : "r"(a[0]), "r"(a[1]), "r"(a[2]), "r"(a[3]), "r"(b[0]), "r"(b[1]));
}

__device__ __forceinline__ void cpa16(uint32_t dst, const void* src){
    asm volatile("cp.async.cg.shared.global [%0], [%1], 16;" :: "r"(dst), "l"(src) : "memory");
}
#define CP_COMMIT() asm volatile("cp.async.commit_group;" ::: "memory")
#define CP_WAIT(n)  asm volatile("cp.async.wait_group %0;" :: "n"(n) : "memory")

// ========================= prep kernels =========================

__global__ void zero_kernel(){
    int i = blockIdx.x*blockDim.x + threadIdx.x;
    if (i < T_*NSPIX*C_) g_sums[i] = 0.f;
    if (i < T_*NSPIX)    g_cnts[i] = 0.f;
}

// W_lin[o, c*49+k] -> g_Wsp[k][hi/lo][swizzled row-major (o,c)]
__global__ void wsplit_kernel(const float* __restrict__ W){
    int i = blockIdx.x*blockDim.x + threadIdx.x;
    if (i >= K2*C_*C_) return;
    int c = i & 63;
    int o = (i >> 6) & 63;
    int k = i >> 12;
    float v = W[o*FAN + c*K2 + k];
    uint32_t u = __float_as_uint(v);
    float hif = __uint_as_float(u & 0xFFFF0000u);   // truncation -> exact residual
    float lof = v - hif;
    // swizzled byte offset: o*128 + ((chunk16) ^ ((o&7)<<4)) + (c&7)*2
    uint32_t boff = (uint32_t)(o*128) + ((((uint32_t)(c>>3))<<4) ^ (((uint32_t)(o&7))<<4)) + (uint32_t)((c&7)*2);
    char* base = (char*)g_Wsp + (size_t)k*16384;
    *(unsigned short*)(base + boff) = (unsigned short)(u >> 16);
    __nv_bfloat16 lb = __float2bfloat16_rn(lof);
    *(__nv_bfloat16*)(base + 8192 + boff) = lb;
}

__global__ void accum_kernel(const float* __restrict__ x, const int* __restrict__ spix){
    int idx = blockIdx.x*blockDim.x + threadIdx.x;
    if (idx >= T_*H_*W_) return;
    int t = idx / (H_*W_);
    int s = spix[idx];
    atomicAdd(&g_cnts[t*NSPIX + s], 1.0f);
    const float* xp = x + (size_t)t*C_*H_*W_ + (idx - t*H_*W_);
    float* dst = &g_sums[(t*NSPIX + s)*C_];
    #pragma unroll 8
    for (int c = 0; c < C_; c++)
        atomicAdd(&dst[c], xp[(size_t)c*H_*W_]);
}

// grid T_*7, 256 threads, dyn smem: down_t[64][196] + sq[196]
__global__ void pwd_kernel(){
    extern __shared__ float sm[];
    float* down_t = sm;
    float* sq = sm + 64*196;
    int t  = blockIdx.x / 7;
    int us = (blockIdx.x % 7) * 28;
    int tid = threadIdx.x;
    for (int i = tid; i < 64*196; i += 256){
        int c = i / 196, s = i - c*196;
        down_t[i] = g_sums[(t*NSPIX + s)*C_ + c] / fmaxf(g_cnts[t*NSPIX + s], 1.f);
    }
    __syncthreads();
    for (int s = tid; s < 196; s += 256){
        float q = 0.f;
        #pragma unroll 8
        for (int c = 0; c < 64; c++){ float v = down_t[c*196 + s]; q += v*v; }
        sq[s] = q;
    }
    __syncthreads();
    for (int tile = tid; tile < 98*14; tile += 256){
        int su = tile % 98, uu = tile / 98;
        int s0 = su*2, u0 = us + uu*2;
        float d00=0.f, d01=0.f, d10=0.f, d11=0.f;
        #pragma unroll 8
        for (int c = 0; c < 64; c++){
            float a0 = down_t[c*196 + s0], a1 = down_t[c*196 + s0 + 1];
            float b0 = down_t[c*196 + u0], b1 = down_t[c*196 + u0 + 1];
            d00 += a0*b0; d01 += a0*b1; d10 += a1*b0; d11 += a1*b1;
        }
        float* dst = &g_pwd[(size_t)(t*NSPIX + s0)*NSPIX];
        dst[u0]         = fmaxf(sq[s0]   + sq[u0]   - 2.f*d00, 0.f);
        dst[u0+1]       = fmaxf(sq[s0]   + sq[u0+1] - 2.f*d01, 0.f);
        dst[NSPIX+u0]   = fmaxf(sq[s0+1] + sq[u0]   - 2.f*d10, 0.f);
        dst[NSPIX+u0+1] = fmaxf(sq[s0+1] + sq[u0+1] - 2.f*d11, 0.f);
    }
}

// ========================= main kernel =========================
// 800 CTAs, 128 threads (4 warps), occ 2. Warp wi: pixels wi*16..wi*16+15, all 64 out chans.

__global__ void __launch_bounds__(128, 2) main_kernel(
    const float* __restrict__ x, const int* __restrict__ spix,
    const float* __restrict__ b_lin, const float* __restrict__ w_scale,
    const float* __restrict__ b_scale, float* __restrict__ out)
{
    extern __shared__ char smem[];
    uint32_t sb = smem_u32(smem);
    int tid = threadIdx.x;
    int wi = tid >> 5, l = tid & 31;
    int t = blockIdx.z;
    int gh0 = blockIdx.y*TH, gw0 = blockIdx.x*TW;

    float* scale_s = (float*)(smem + OFF_SCALE);
    float* rw      = (float*)(smem + OFF_RW);

    // ---- phase 1: per-pixel scale = 10*softplus(dot(w_scale, xn) + b0) ----
    if (tid < NPIX){
        int gh = gh0 + tid/TW, gw = gw0 + (tid % TW);
        const float* xp = x + (size_t)t*C_*H_*W_ + gh*W_ + gw;
        float nsq = 0.f, dot = 0.f;
        #pragma unroll 8
        for (int c = 0; c < C_; c++){
            float v = xp[(size_t)c*H_*W_];
            nsq += v*v;
            dot += w_scale[c]*v;
        }
        float z  = dot / (sqrtf(nsq) + 1e-10f) + b_scale[0];
        float sp = fmaxf(z, 0.f) + log1pf(expf(-fabsf(z)));
        scale_s[tid] = 10.f * sp;
    }

    // ---- phase 2: halo load + hi/lo bf16 split: row s = [hi 128B][lo 128B][pad16] ----
    for (int i = tid; i < NS*32; i += 128){
        int s  = i >> 5;          // 0..195
        int cp = i & 31;          // channel pair
        int rr = s / XC, cc2 = s - rr*XC;
        int gh = refl(gh0 + rr - 3, H_), gw = refl(gw0 + cc2 - 3, W_);
        const float* xp = x + ((size_t)(t*C_ + 2*cp)*H_ + gh)*W_ + gw;
        float v0 = xp[0], v1 = xp[(size_t)H_*W_];
        uint32_t u0 = __float_as_uint(v0), u1 = __float_as_uint(v1);
        uint32_t hp = __byte_perm(u0, u1, 0x7632);     // {u0>>16, u1>>16}
        float l0 = v0 - __uint_as_float(u0 & 0xFFFF0000u);
        float l1 = v1 - __uint_as_float(u1 & 0xFFFF0000u);
        __nv_bfloat162 lp2 = __floats2bfloat162_rn(l0, l1);
        *(uint32_t*)(smem + OFF_HALO + s*HROW + cp*4)       = hp;
        *(uint32_t*)(smem + OFF_HALO + s*HROW + 128 + cp*4) = *(uint32_t*)&lp2;
    }
    __syncthreads();

    // ---- phase 3: rw[p][k] = exp(-scale_p * pwd[s_center, nb_k]), then max-normalize ----
    for (int item = tid; item < NPIX*K2; item += 128){
        int p  = item / K2, k = item - p*K2;
        int ki = k / KS,  kj = k - ki*KS;
        int gh = gh0 + p/TW, gw = gw0 + (p % TW);
        int rh = refl(gh + ki - 3, H_), rc = refl(gw + kj - 3, W_);
        int sc = spix[(t*H_ + gh)*W_ + gw];
        int nb = spix[(t*H_ + rh)*W_ + rc];
        rw[item] = expf(-scale_s[p] * g_pwd[(size_t)(t*NSPIX + sc)*NSPIX + nb]);
    }
    __syncthreads();
    if (tid < NPIX){
        float m = 0.f;
        #pragma unroll
        for (int k = 0; k < K2; k++) m = fmaxf(m, rw[tid*K2 + k]);
        float inv = 1.f / (1e-5f + m);
        #pragma unroll
        for (int k = 0; k < K2; k++) rw[tid*K2 + k] *= inv;
    }

    // ---- per-lane static addressing ----
    // A (m16x16 tile via ldmatrix.x4): lanes 0-7 rows0-7|col0, 8-15 rows8-15|col0,
    //                                  16-23 rows0-7|col16B, 24-31 rows8-15|col16B
    int rowA  = (l & 7) | (((l >> 3) & 1) << 3);   // 0..15
    int colhA = (l >> 4) & 1;
    int pA    = wi*16 + rowA;                       // pixel for this lane's A row
    uint32_t aStat = sb + OFF_HALO + (uint32_t)(((pA >> 3)*XC + (pA & 7))*HROW) + colhA*16;
    // B ([n][k] row-major, XOR-swizzled): x4 covers two n8 tiles
    int oRow  = (l & 7) | (((l >> 4) & 1) << 3);   // 0..15 within n16 pair
    int bhalf = (l >> 3) & 1;                       // k half (16B)
    int p_lo = wi*16 + (l >> 2);                    // accumulator row (d0,d1)
    // p_hi = p_lo + 8 (d2,d3)

    // ---- preload B for k=0 ----
    {
        const char* src = (const char*)g_Wsp;
        uint32_t dst = sb + OFF_B;
        #pragma unroll
        for (int j = 0; j < 8; j++){
            int idx = tid + j*128;
            cpa16(dst + idx*16, src + idx*16);
        }
        CP_COMMIT();
    }

    float acc[8][4];
    #pragma unroll
    for (int nt = 0; nt < 8; nt++)
        #pragma unroll
        for (int q = 0; q < 4; q++) acc[nt][q] = 0.f;

    // ---- main loop over 49 kernel offsets ----
    for (int k = 0; k < K2; k++){
        int buf = k & 1;
        if (k + 1 < K2){
            const char* src = (const char*)g_Wsp + (size_t)(k+1)*16384;
            uint32_t dst = sb + OFF_B + (buf^1)*16384;
            #pragma unroll
            for (int j = 0; j < 8; j++){
                int idx = tid + j*128;
                cpa16(dst + idx*16, src + idx*16);
            }
            CP_COMMIT();
            CP_WAIT(1);
        } else {
            CP_WAIT(0);
        }
        __syncthreads();

        int ki = k / KS, kj = k - ki*KS;
        uint32_t aBase = aStat + (uint32_t)((ki*XC + kj)*HROW);
        uint32_t bBase = sb + OFF_B + buf*16384;

        float d[8][4];
        #pragma unroll
        for (int nt = 0; nt < 8; nt++)
            #pragma unroll
            for (int q = 0; q < 4; q++) d[nt][q] = 0.f;

        #pragma unroll
        for (int kc = 0; kc < 4; kc++){
            uint32_t aH[4], aL[4];
            ldsm4(aH, aBase + kc*32);
            ldsm4(aL, aBase + 128 + kc*32);
            #pragma unroll
            for (int nt2 = 0; nt2 < 4; nt2++){
                int o = nt2*16 + oRow;
                uint32_t csw = (uint32_t)((kc*32 + bhalf*16) ^ ((o & 7) << 4));
                uint32_t bAddr = bBase + (uint32_t)(o*128) + csw;
                uint32_t bH[4], bL[4];
                ldsm4(bH, bAddr);
                ldsm4(bL, bAddr + 8192);
                mma16816(d[2*nt2],   aH, bH);
                mma16816(d[2*nt2+1], aH, bH+2);
                mma16816(d[2*nt2],   aL, bH);
                mma16816(d[2*nt2+1], aL, bH+2);
                mma16816(d[2*nt2],   aH, bL);
                mma16816(d[2*nt2+1], aH, bL+2);
            }
        }

        // epilogue-weight this k's partial by rw (rows t/4 and t/4+8)
        float r_lo = rw[p_lo*K2 + k];
        float r_hi = rw[(p_lo+8)*K2 + k];
        #pragma unroll
        for (int nt = 0; nt < 8; nt++){
            acc[nt][0] += r_lo*d[nt][0];
            acc[nt][1] += r_lo*d[nt][1];
            acc[nt][2] += r_hi*d[nt][2];
            acc[nt][3] += r_hi*d[nt][3];
        }
        __syncthreads();
    }

    // ---- store ----
    {
        int gh_lo = gh0 + (p_lo >> 3),     gw_lo = gw0 + (p_lo & 7);
        int p_hi = p_lo + 8;
        int gh_hi = gh0 + (p_hi >> 3),     gw_hi = gw0 + (p_hi & 7);
        #pragma unroll
        for (int nt = 0; nt < 8; nt++){
            int o = nt*8 + 2*(l & 3);
            float b0 = b_lin[o], b1 = b_lin[o+1];
            float* lo0 = out + ((size_t)(t*C_ + o  )*H_ + gh_lo)*W_ + gw_lo;
            float* lo1 = out + ((size_t)(t*C_ + o+1)*H_ + gh_lo)*W_ + gw_lo;
            float* hi0 = out + ((size_t)(t*C_ + o  )*H_ + gh_hi)*W_ + gw_hi;
            float* hi1 = out + ((size_t)(t*C_ + o+1)*H_ + gh_hi)*W_ + gw_hi;
            *lo0 = acc[nt][0] + b0;
            *lo1 = acc[nt][1] + b1;
            *hi0 = acc[nt][2] + b0;
            *hi1 = acc[nt][3] + b1;
        }
    }
}

// ========================= launch =========================

extern "C" void kernel_launch(void* const* d_in, const int* in_sizes, int n_in,
                              void* d_out, int out_size)
{
    const float* x       = (const float*)d_in[0];
    const int*   spix    = (const int*)  d_in[1];
    const float* W       = (const float*)d_in[2];
    const float* b_lin   = (const float*)d_in[3];
    const float* w_scale = (const float*)d_in[4];
    const float* b_scale = (const float*)d_in[5];
    float* out = (float*)d_out;

    cudaFuncSetAttribute(pwd_kernel,  cudaFuncAttributeMaxDynamicSharedMemorySize, PWD_SMEM);
    cudaFuncSetAttribute(main_kernel, cudaFuncAttributeMaxDynamicSharedMemorySize, SMEM_MAIN);

    zero_kernel  <<<(T_*NSPIX*C_ + 255)/256, 256>>>();
    wsplit_kernel<<<(K2*C_*C_   + 255)/256, 256>>>(W);
    accum_kernel <<<(T_*H_*W_   + 255)/256, 256>>>(x, spix);
    pwd_kernel   <<<T_*7, 256, PWD_SMEM>>>();

    dim3 grid(W_/TW, H_/TH, T_);
    main_kernel<<<grid, 128, SMEM_MAIN>>>(x, spix, b_lin, w_scale, b_scale, out);
}